// round 13
// baseline (speedup 1.0000x reference)
#include <cuda_runtime.h>
#include <math.h>
#include <stdint.h>

#define BATCH   65536
#define IN_DIM  512
#define LATENT  32
#define NTRI    528
#define NPAD    544            // W_ch padded row (floats)
#define WENC_PAD 524           // conflict-free float4 weight rows
#define THREADS 512
#define WARPS   16
#define RPW     4
#define TILE_ROWS (WARPS*RPW)  // 64
#define NTILES  (BATCH/TILE_ROWS) // 1024
#define GRID    152

#define XH      272            // per-row stride (floats) of half-K x stage
#define LOFF_B  560            // cov buffer-B offset (bank set differs by 16 from A)
#define WBUF_FLOATS 1088       // per-warp buffer: 4x272 x-halves OR two packed-tri L rows

// ---- smem layout (floats) ----
#define OFF_WENC 0
#define SZ_WENC  (LATENT*WENC_PAD)              // 16768
#define OFF_WCH  (OFF_WENC + SZ_WENC)           // 16768
#define SZ_WCH   (LATENT*NPAD)                  // 17408
#define OFF_WMU  (OFF_WCH + SZ_WCH)             // 34176
#define OFF_BENC (OFF_WMU + LATENT*LATENT)      // 35200
#define OFF_BMU  (OFF_BENC + 32)                // 35232
#define OFF_BCH  (OFF_BMU + 32)                 // 35264 (544)
#define OFF_S    (OFF_BCH + NPAD)               // 35808
#define OFF_WBUF (OFF_S + 32)                   // 35840 (16B aligned)
#define SMEM_FLOATS (OFF_WBUF + WARPS*WBUF_FLOATS) // 53248 floats = 212992 B

#define MU_OFF  ((size_t)BATCH*LATENT)
#define COV_OFF ((size_t)BATCH*LATENT*2)

__device__ __forceinline__ float lrelu(float v) { return v >= 0.f ? v : 0.01f * v; }
// softplus -> clip -> +0.01 (applied to already-lrelu'ed diag value)
__device__ __forceinline__ float dclip(float d) {
    float sp = (d > 20.f) ? d : log1pf(expf(d));
    return fminf(fmaxf(sp, 0.001f), 100.f) + 0.01f;
}

// Per-chunk lane masks of diagonal elements e = i*(i+3)/2 (e = cc*32 + lane)
__device__ __constant__ const unsigned kDiagMask[17] = {
    0x08104225u, 0x00401008u, 0x04002002u, 0x00800100u, 0x01000080u,
    0x20000400u, 0x00020000u, 0x10000040u, 0x00080000u, 0x00000800u,
    0x40000010u, 0x02000000u, 0x00200000u, 0x00040000u, 0x00010000u,
    0x00008000u, 0x00008000u
};

__global__ void __launch_bounds__(THREADS)
pm_kernel(const float* __restrict__ x,       const float* __restrict__ W_enc,
          const float* __restrict__ b_enc,   const float* __restrict__ bn_gamma,
          const float* __restrict__ bn_beta, const float* __restrict__ bn_mean,
          const float* __restrict__ bn_var,  const float* __restrict__ W_mu,
          const float* __restrict__ b_mu,    const float* __restrict__ W_ch,
          const float* __restrict__ b_ch,    float* __restrict__ out)
{
    extern __shared__ float sm[];
    const int tid = threadIdx.x;

    // ---- stage + fold weights into smem ----
    if (tid < 32) {
        float s = bn_gamma[tid] * rsqrtf(bn_var[tid] + 1e-5f);
        sm[OFF_S + tid]    = s;
        sm[OFF_BENC + tid] = (b_enc[tid] - bn_mean[tid]) * s + bn_beta[tid];
        sm[OFF_BMU + tid]  = b_mu[tid];
    }
    __syncthreads();
    for (int idx = tid; idx < IN_DIM * LATENT; idx += THREADS) {
        int k = idx >> 5, j = idx & 31;
        sm[OFF_WENC + j * WENC_PAD + k] = W_enc[idx] * sm[OFF_S + j];  // transposed + BN fold
    }
    for (int idx = tid; idx < LATENT * NPAD; idx += THREADS) {
        int k = idx / NPAD, c = idx - k * NPAD;
        sm[OFF_WCH + idx] = (c < NTRI) ? W_ch[k * NTRI + c] : 0.f;
    }
    for (int idx = tid; idx < LATENT * LATENT; idx += THREADS) sm[OFF_WMU + idx] = W_mu[idx];
    for (int idx = tid; idx < NPAD; idx += THREADS) sm[OFF_BCH + idx] = (idx < NTRI) ? b_ch[idx] : 0.f;
    __syncthreads();

    const int warp = tid >> 5, lane = tid & 31;
    float* xw = sm + OFF_WBUF + warp * WBUF_FLOATS;   // x half stage / two L buffers
    const float* wrow = sm + OFF_WENC + lane * WENC_PAD;
    const float bj = sm[OFF_BENC + lane];
    const float bm = sm[OFF_BMU + lane];

    // cov half-split lane mapping (round-10 proven)
    const int ch   = lane & 15;
    const int ch2  = ch + 16;
    float* Lbh = xw + (lane >> 4) * LOFF_B;
    const int triC  = (ch  * (ch  + 1)) >> 1;
    const int triC2 = (ch2 * (ch2 + 1)) >> 1;

    for (int tile = blockIdx.x; tile < NTILES; tile += gridDim.x) {
        const int rbase = tile * TILE_ROWS + warp * RPW;

        // ---- enc GEMM in two half-K passes, second half prefetched ----
        float h0 = 0.f, h1 = 0.f, h2 = 0.f, h3 = 0.f;
        float4 pv[8];
        #pragma unroll
        for (int r = 0; r < RPW; r++)
            #pragma unroll
            for (int c = 0; c < 2; c++)
                pv[r * 2 + c] = *(const float4*)(x + (size_t)(rbase + r) * IN_DIM + c * 128 + lane * 4);

        #pragma unroll
        for (int half = 0; half < 2; half++) {
            #pragma unroll
            for (int r = 0; r < RPW; r++)
                #pragma unroll
                for (int c = 0; c < 2; c++)
                    *(float4*)(xw + r * XH + c * 128 + lane * 4) = pv[r * 2 + c];
            __syncwarp();
            if (half == 0) {            // prefetch half 1 while computing half 0
                #pragma unroll
                for (int r = 0; r < RPW; r++)
                    #pragma unroll
                    for (int c = 0; c < 2; c++)
                        pv[r * 2 + c] = *(const float4*)(x + (size_t)(rbase + r) * IN_DIM + 256 + c * 128 + lane * 4);
            }
            const float* wh = wrow + half * 256;
            #pragma unroll 4
            for (int k = 0; k < 256; k += 4) {
                float4 wv = *(const float4*)(wh + k);
                float4 a0 = *(const float4*)(xw + 0 * XH + k);
                float4 a1 = *(const float4*)(xw + 1 * XH + k);
                float4 a2 = *(const float4*)(xw + 2 * XH + k);
                float4 a3 = *(const float4*)(xw + 3 * XH + k);
                h0 = fmaf(a0.x, wv.x, h0); h0 = fmaf(a0.y, wv.y, h0); h0 = fmaf(a0.z, wv.z, h0); h0 = fmaf(a0.w, wv.w, h0);
                h1 = fmaf(a1.x, wv.x, h1); h1 = fmaf(a1.y, wv.y, h1); h1 = fmaf(a1.z, wv.z, h1); h1 = fmaf(a1.w, wv.w, h1);
                h2 = fmaf(a2.x, wv.x, h2); h2 = fmaf(a2.y, wv.y, h2); h2 = fmaf(a2.z, wv.z, h2); h2 = fmaf(a2.w, wv.w, h2);
                h3 = fmaf(a3.x, wv.x, h3); h3 = fmaf(a3.y, wv.y, h3); h3 = fmaf(a3.z, wv.z, h3); h3 = fmaf(a3.w, wv.w, h3);
            }
            __syncwarp();
        }
        h0 = lrelu(h0 + bj); h1 = lrelu(h1 + bj); h2 = lrelu(h2 + bj); h3 = lrelu(h3 + bj);
        out[(size_t)(rbase + 0) * 32 + lane] = h0;
        out[(size_t)(rbase + 1) * 32 + lane] = h1;
        out[(size_t)(rbase + 2) * 32 + lane] = h2;
        out[(size_t)(rbase + 3) * 32 + lane] = h3;

        // ---- mu + ch GEMMs (scalar, round-10 proven) ----
        float amu0 = 0.f, amu1 = 0.f, amu2 = 0.f, amu3 = 0.f;
        float ac[RPW][17];
        #pragma unroll
        for (int r = 0; r < RPW; r++)
            #pragma unroll
            for (int c = 0; c < 17; c++) ac[r][c] = 0.f;

        #pragma unroll 2
        for (int k = 0; k < LATENT; k++) {
            float hv0 = __shfl_sync(0xffffffffu, h0, k);
            float hv1 = __shfl_sync(0xffffffffu, h1, k);
            float hv2 = __shfl_sync(0xffffffffu, h2, k);
            float hv3 = __shfl_sync(0xffffffffu, h3, k);
            float wm = sm[OFF_WMU + k * 32 + lane];
            amu0 = fmaf(hv0, wm, amu0); amu1 = fmaf(hv1, wm, amu1);
            amu2 = fmaf(hv2, wm, amu2); amu3 = fmaf(hv3, wm, amu3);
            const float* wck = sm + OFF_WCH + k * NPAD + lane;
            #pragma unroll
            for (int c = 0; c < 17; c++) {
                float wc = wck[c * 32];
                ac[0][c] = fmaf(hv0, wc, ac[0][c]);
                ac[1][c] = fmaf(hv1, wc, ac[1][c]);
                ac[2][c] = fmaf(hv2, wc, ac[2][c]);
                ac[3][c] = fmaf(hv3, wc, ac[3][c]);
            }
        }
        out[MU_OFF + (size_t)(rbase + 0) * 32 + lane] = lrelu(amu0 + bm);
        out[MU_OFF + (size_t)(rbase + 1) * 32 + lane] = lrelu(amu1 + bm);
        out[MU_OFF + (size_t)(rbase + 2) * 32 + lane] = lrelu(amu2 + bm);
        out[MU_OFF + (size_t)(rbase + 3) * 32 + lane] = lrelu(amu3 + bm);
        __syncwarp();   // enc reads of xw done

        // ---- cov: 2 batch rows per pass, diag inlined into scatter ----
        float* LbA = xw;
        float* LbB = xw + LOFF_B;
        #pragma unroll
        for (int p = 0; p < 2; p++) {
            // scatter elts for both rows; apply softplus-clip inline on diag elements
            #pragma unroll
            for (int cc = 0; cc < 17; cc++) {
                int e = cc * 32 + lane;
                if (cc == 16 && e >= NTRI) continue;
                float bc = sm[OFF_BCH + e];
                float vA = lrelu(ac[2 * p + 0][cc] + bc);
                float vB = lrelu(ac[2 * p + 1][cc] + bc);
                if ((kDiagMask[cc] >> lane) & 1u) { vA = dclip(vA); vB = dclip(vB); }
                LbA[e] = vA;
                LbB[e] = vB;
            }
            __syncwarp();
            // gather own rows (cols ch, ch+16) from own-half buffer; zeros beyond row end
            float Lk1[16], Lk2[32];
            #pragma unroll
            for (int j = 0; j < 16; j++) Lk1[j] = (j <= ch)  ? Lbh[triC  + j] : 0.f;
            #pragma unroll
            for (int j = 0; j < 32; j++) Lk2[j] = (j <= ch2) ? Lbh[triC2 + j] : 0.f;

            float* oc = out + COV_OFF + (size_t)(rbase + 2 * p + (lane >> 4)) * 1024;
            #pragma unroll
            for (int i = 0; i < 32; i++) {
                const float* Lr = Lbh + ((i * (i + 1)) >> 1);
                float a1a = 0.f, a1b = 0.f, a2a = 0.f, a2b = 0.f;
                #pragma unroll
                for (int j = 0; j <= i; j++) {
                    float lv = Lr[j];           // half-split broadcast: 1 wf, 2 rows
                    if (j < 16) {
                        if (j & 1) a1b = fmaf(Lk1[j], lv, a1b);
                        else       a1a = fmaf(Lk1[j], lv, a1a);
                    }
                    if (j & 1) a2b = fmaf(Lk2[j], lv, a2b);
                    else       a2a = fmaf(Lk2[j], lv, a2a);
                }
                float cv1 = a1a + a1b;
                float cv2 = a2a + a2b;
                if (i == ch)  cv1 += 0.01f;
                if (i == ch2) cv2 += 0.01f;
                oc[i * 32 + ch]  = cv1;
                oc[i * 32 + ch2] = cv2;
            }
            __syncwarp();   // cov reads done before next scatter / next tile x stage
        }
    }
}

extern "C" void kernel_launch(void* const* d_in, const int* in_sizes, int n_in,
                              void* d_out, int out_size)
{
    (void)in_sizes; (void)n_in; (void)out_size;
    const float* x        = (const float*)d_in[0];
    const float* W_enc    = (const float*)d_in[1];
    const float* b_enc    = (const float*)d_in[2];
    const float* bn_gamma = (const float*)d_in[3];
    const float* bn_beta  = (const float*)d_in[4];
    const float* bn_mean  = (const float*)d_in[5];
    const float* bn_var   = (const float*)d_in[6];
    const float* W_mu     = (const float*)d_in[7];
    const float* b_mu     = (const float*)d_in[8];
    const float* W_ch     = (const float*)d_in[9];
    const float* b_ch     = (const float*)d_in[10];
    float* out = (float*)d_out;

    cudaFuncSetAttribute(pm_kernel, cudaFuncAttributeMaxDynamicSharedMemorySize,
                         SMEM_FLOATS * (int)sizeof(float));
    pm_kernel<<<GRID, THREADS, SMEM_FLOATS * sizeof(float)>>>(
        x, W_enc, b_enc, bn_gamma, bn_beta, bn_mean, bn_var,
        W_mu, b_mu, W_ch, b_ch, out);
}

// round 14
// speedup vs baseline: 1.1669x; 1.1669x over previous
#include <cuda_runtime.h>
#include <math.h>
#include <stdint.h>

#define BATCH   65536
#define IN_DIM  512
#define LATENT  32
#define NTRI    528
#define NPAD    544            // W_ch padded row (floats)
#define WENC_PAD 524           // conflict-free float4 weight rows
#define THREADS 512
#define WARPS   16
#define RPW     4
#define TILE_ROWS (WARPS*RPW)  // 64
#define NTILES  (BATCH/TILE_ROWS) // 1024
#define GRID    152

#define XH      272            // per-row stride (floats) of half-K x stage
#define LOFF_B  560            // cov buffer-B offset (bank set differs by 16 from A)
#define WBUF_FLOATS 1088       // per-warp buffer: 4x272 x-halves OR two packed-tri L rows

// ---- smem layout (floats) ----
#define OFF_WENC 0
#define SZ_WENC  (LATENT*WENC_PAD)              // 16768
#define OFF_WCH  (OFF_WENC + SZ_WENC)           // 16768
#define SZ_WCH   (LATENT*NPAD)                  // 17408
#define OFF_WMU  (OFF_WCH + SZ_WCH)             // 34176
#define OFF_BENC (OFF_WMU + LATENT*LATENT)      // 35200
#define OFF_BMU  (OFF_BENC + 32)                // 35232
#define OFF_BCH  (OFF_BMU + 32)                 // 35264 (544)
#define OFF_S    (OFF_BCH + NPAD)               // 35808
#define OFF_WBUF (OFF_S + 32)                   // 35840 (16B aligned)
#define SMEM_FLOATS (OFF_WBUF + WARPS*WBUF_FLOATS) // 53248 floats = 212992 B

#define MU_OFF  ((size_t)BATCH*LATENT)
#define COV_OFF ((size_t)BATCH*LATENT*2)

__device__ __forceinline__ float lrelu(float v) { return v >= 0.f ? v : 0.01f * v; }

__global__ void __launch_bounds__(THREADS)
pm_kernel(const float* __restrict__ x,       const float* __restrict__ W_enc,
          const float* __restrict__ b_enc,   const float* __restrict__ bn_gamma,
          const float* __restrict__ bn_beta, const float* __restrict__ bn_mean,
          const float* __restrict__ bn_var,  const float* __restrict__ W_mu,
          const float* __restrict__ b_mu,    const float* __restrict__ W_ch,
          const float* __restrict__ b_ch,    float* __restrict__ out)
{
    extern __shared__ float sm[];
    const int tid = threadIdx.x;

    // ---- stage + fold weights into smem ----
    if (tid < 32) {
        float s = bn_gamma[tid] * rsqrtf(bn_var[tid] + 1e-5f);
        sm[OFF_S + tid]    = s;
        sm[OFF_BENC + tid] = (b_enc[tid] - bn_mean[tid]) * s + bn_beta[tid];
        sm[OFF_BMU + tid]  = b_mu[tid];
    }
    __syncthreads();
    for (int idx = tid; idx < IN_DIM * LATENT; idx += THREADS) {
        int k = idx >> 5, j = idx & 31;
        sm[OFF_WENC + j * WENC_PAD + k] = W_enc[idx] * sm[OFF_S + j];  // transposed + BN fold
    }
    for (int idx = tid; idx < LATENT * NPAD; idx += THREADS) {
        int k = idx / NPAD, c = idx - k * NPAD;
        sm[OFF_WCH + idx] = (c < NTRI) ? W_ch[k * NTRI + c] : 0.f;
    }
    for (int idx = tid; idx < LATENT * LATENT; idx += THREADS) sm[OFF_WMU + idx] = W_mu[idx];
    for (int idx = tid; idx < NPAD; idx += THREADS) sm[OFF_BCH + idx] = (idx < NTRI) ? b_ch[idx] : 0.f;
    __syncthreads();

    const int warp = tid >> 5, lane = tid & 31;
    float* xw = sm + OFF_WBUF + warp * WBUF_FLOATS;   // x half stage / two L buffers
    const float* wrow = sm + OFF_WENC + lane * WENC_PAD;
    const float bj = sm[OFF_BENC + lane];
    const float bm = sm[OFF_BMU + lane];

    // cov half-split lane mapping (round-10 proven)
    const int ch   = lane & 15;                 // base column (0..15)
    const int ch2  = ch + 16;                   // high column
    float* Lbh = xw + (lane >> 4) * LOFF_B;     // own-half L buffer (A or B)
    const int triC  = (ch  * (ch  + 1)) >> 1;
    const int triC2 = (ch2 * (ch2 + 1)) >> 1;

    for (int tile = blockIdx.x; tile < NTILES; tile += gridDim.x) {
        const int rbase = tile * TILE_ROWS + warp * RPW;

        // ---- enc GEMM in two half-K passes, second half prefetched ----
        float h0 = 0.f, h1 = 0.f, h2 = 0.f, h3 = 0.f;
        float4 pv[8];
        #pragma unroll
        for (int r = 0; r < RPW; r++)
            #pragma unroll
            for (int c = 0; c < 2; c++)
                pv[r * 2 + c] = *(const float4*)(x + (size_t)(rbase + r) * IN_DIM + c * 128 + lane * 4);

        #pragma unroll
        for (int half = 0; half < 2; half++) {
            #pragma unroll
            for (int r = 0; r < RPW; r++)
                #pragma unroll
                for (int c = 0; c < 2; c++)
                    *(float4*)(xw + r * XH + c * 128 + lane * 4) = pv[r * 2 + c];
            __syncwarp();
            if (half == 0) {            // prefetch half 1 while computing half 0
                #pragma unroll
                for (int r = 0; r < RPW; r++)
                    #pragma unroll
                    for (int c = 0; c < 2; c++)
                        pv[r * 2 + c] = *(const float4*)(x + (size_t)(rbase + r) * IN_DIM + 256 + c * 128 + lane * 4);
            }
            const float* wh = wrow + half * 256;
            #pragma unroll 4
            for (int k = 0; k < 256; k += 4) {
                float4 wv = *(const float4*)(wh + k);
                float4 a0 = *(const float4*)(xw + 0 * XH + k);
                float4 a1 = *(const float4*)(xw + 1 * XH + k);
                float4 a2 = *(const float4*)(xw + 2 * XH + k);
                float4 a3 = *(const float4*)(xw + 3 * XH + k);
                h0 = fmaf(a0.x, wv.x, h0); h0 = fmaf(a0.y, wv.y, h0); h0 = fmaf(a0.z, wv.z, h0); h0 = fmaf(a0.w, wv.w, h0);
                h1 = fmaf(a1.x, wv.x, h1); h1 = fmaf(a1.y, wv.y, h1); h1 = fmaf(a1.z, wv.z, h1); h1 = fmaf(a1.w, wv.w, h1);
                h2 = fmaf(a2.x, wv.x, h2); h2 = fmaf(a2.y, wv.y, h2); h2 = fmaf(a2.z, wv.z, h2); h2 = fmaf(a2.w, wv.w, h2);
                h3 = fmaf(a3.x, wv.x, h3); h3 = fmaf(a3.y, wv.y, h3); h3 = fmaf(a3.z, wv.z, h3); h3 = fmaf(a3.w, wv.w, h3);
            }
            __syncwarp();
        }
        h0 = lrelu(h0 + bj); h1 = lrelu(h1 + bj); h2 = lrelu(h2 + bj); h3 = lrelu(h3 + bj);
        out[(size_t)(rbase + 0) * 32 + lane] = h0;
        out[(size_t)(rbase + 1) * 32 + lane] = h1;
        out[(size_t)(rbase + 2) * 32 + lane] = h2;
        out[(size_t)(rbase + 3) * 32 + lane] = h3;

        // ---- mu + ch GEMMs (scalar, round-10 proven) ----
        float amu0 = 0.f, amu1 = 0.f, amu2 = 0.f, amu3 = 0.f;
        float ac[RPW][17];
        #pragma unroll
        for (int r = 0; r < RPW; r++)
            #pragma unroll
            for (int c = 0; c < 17; c++) ac[r][c] = 0.f;

        #pragma unroll 2
        for (int k = 0; k < LATENT; k++) {
            float hv0 = __shfl_sync(0xffffffffu, h0, k);
            float hv1 = __shfl_sync(0xffffffffu, h1, k);
            float hv2 = __shfl_sync(0xffffffffu, h2, k);
            float hv3 = __shfl_sync(0xffffffffu, h3, k);
            float wm = sm[OFF_WMU + k * 32 + lane];
            amu0 = fmaf(hv0, wm, amu0); amu1 = fmaf(hv1, wm, amu1);
            amu2 = fmaf(hv2, wm, amu2); amu3 = fmaf(hv3, wm, amu3);
            const float* wck = sm + OFF_WCH + k * NPAD + lane;
            #pragma unroll
            for (int c = 0; c < 17; c++) {
                float wc = wck[c * 32];
                ac[0][c] = fmaf(hv0, wc, ac[0][c]);
                ac[1][c] = fmaf(hv1, wc, ac[1][c]);
                ac[2][c] = fmaf(hv2, wc, ac[2][c]);
                ac[3][c] = fmaf(hv3, wc, ac[3][c]);
            }
        }
        out[MU_OFF + (size_t)(rbase + 0) * 32 + lane] = lrelu(amu0 + bm);
        out[MU_OFF + (size_t)(rbase + 1) * 32 + lane] = lrelu(amu1 + bm);
        out[MU_OFF + (size_t)(rbase + 2) * 32 + lane] = lrelu(amu2 + bm);
        out[MU_OFF + (size_t)(rbase + 3) * 32 + lane] = lrelu(amu3 + bm);
        __syncwarp();   // enc reads of xw done

        // ---- cov: 2 batch rows per pass via half-split broadcasts (round-10 proven) ----
        float* LbA = xw;            // packed-tri L of even row   [0, 528)
        float* LbB = xw + LOFF_B;   // packed-tri L of odd row    [560, 1088)
        #pragma unroll
        for (int p = 0; p < 2; p++) {
            // scatter elts for both rows (full warp, packed-tri offset == element index)
            #pragma unroll
            for (int cc = 0; cc < 17; cc++) {
                int e = cc * 32 + lane;
                if (cc == 16 && e >= NTRI) continue;
                float bc = sm[OFF_BCH + e];
                LbA[e] = lrelu(ac[2 * p + 0][cc] + bc);
                LbB[e] = lrelu(ac[2 * p + 1][cc] + bc);
            }
            __syncwarp();
            // diag transform (lane = L-row), both buffers
            {
                int dio = ((lane * (lane + 1)) >> 1) + lane;
                float d = LbA[dio];
                float sp = (d > 20.f) ? d : log1pf(expf(d));
                LbA[dio] = fminf(fmaxf(sp, 0.001f), 100.f) + 0.01f;
                d = LbB[dio];
                sp = (d > 20.f) ? d : log1pf(expf(d));
                LbB[dio] = fminf(fmaxf(sp, 0.001f), 100.f) + 0.01f;
            }
            __syncwarp();
            // gather own rows (cols ch, ch+16) from own-half buffer; zeros beyond row end
            float Lk1[16], Lk2[32];
            #pragma unroll
            for (int j = 0; j < 16; j++) Lk1[j] = (j <= ch)  ? Lbh[triC  + j] : 0.f;
            #pragma unroll
            for (int j = 0; j < 32; j++) Lk2[j] = (j <= ch2) ? Lbh[triC2 + j] : 0.f;

            float* oc = out + COV_OFF + (size_t)(rbase + 2 * p + (lane >> 4)) * 1024;
            #pragma unroll
            for (int i = 0; i < 32; i++) {
                const float* Lr = Lbh + ((i * (i + 1)) >> 1);
                float a1a = 0.f, a1b = 0.f, a2a = 0.f, a2b = 0.f;
                #pragma unroll
                for (int j = 0; j <= i; j++) {
                    float lv = Lr[j];               // half-split broadcast: 1 wf for both rows
                    if (j < 16) {
                        if (j & 1) a1b = fmaf(Lk1[j], lv, a1b);
                        else       a1a = fmaf(Lk1[j], lv, a1a);
                    }
                    if (j & 1) a2b = fmaf(Lk2[j], lv, a2b);
                    else       a2a = fmaf(Lk2[j], lv, a2a);
                }
                float cv1 = a1a + a1b;
                float cv2 = a2a + a2b;
                if (i == ch)  cv1 += 0.01f;
                if (i == ch2) cv2 += 0.01f;
                oc[i * 32 + ch]  = cv1;
                oc[i * 32 + ch2] = cv2;
            }
            __syncwarp();   // cov reads done before next scatter / next tile x stage
        }
    }
}

extern "C" void kernel_launch(void* const* d_in, const int* in_sizes, int n_in,
                              void* d_out, int out_size)
{
    (void)in_sizes; (void)n_in; (void)out_size;
    const float* x        = (const float*)d_in[0];
    const float* W_enc    = (const float*)d_in[1];
    const float* b_enc    = (const float*)d_in[2];
    const float* bn_gamma = (const float*)d_in[3];
    const float* bn_beta  = (const float*)d_in[4];
    const float* bn_mean  = (const float*)d_in[5];
    const float* bn_var   = (const float*)d_in[6];
    const float* W_mu     = (const float*)d_in[7];
    const float* b_mu     = (const float*)d_in[8];
    const float* W_ch     = (const float*)d_in[9];
    const float* b_ch     = (const float*)d_in[10];
    float* out = (float*)d_out;

    cudaFuncSetAttribute(pm_kernel, cudaFuncAttributeMaxDynamicSharedMemorySize,
                         SMEM_FLOATS * (int)sizeof(float));
    pm_kernel<<<GRID, THREADS, SMEM_FLOATS * sizeof(float)>>>(
        x, W_enc, b_enc, bn_gamma, bn_beta, bn_mean, bn_var,
        W_mu, b_mu, W_ch, b_ch, out);
}

// round 15
// speedup vs baseline: 1.1797x; 1.0109x over previous
#include <cuda_runtime.h>
#include <math.h>
#include <stdint.h>

#define BATCH   65536
#define IN_DIM  512
#define LATENT  32
#define NTRI    528
#define NPAD    544            // W_ch padded row (floats)
#define WENC_PAD 524           // conflict-free float4 weight rows
#define THREADS 512
#define WARPS   16
#define RPW     4
#define TILE_ROWS (WARPS*RPW)  // 64
#define NTILES  (BATCH/TILE_ROWS) // 1024
#define GRID    152

#define XH      272            // per-row stride (floats) of half-K x stage
#define LOFF_B  560            // cov buffer-B offset (bank set differs by 16 from A)
#define WBUF_FLOATS 1088       // per-warp buffer: 4x272 x-halves OR two packed-tri L rows

// ---- smem layout (floats) ----
#define OFF_WENC 0
#define SZ_WENC  (LATENT*WENC_PAD)              // 16768
#define OFF_WCH  (OFF_WENC + SZ_WENC)           // 16768 (col-pair interleaved, 544/row)
#define SZ_WCH   (LATENT*NPAD)                  // 17408
#define OFF_WMU  (OFF_WCH + SZ_WCH)             // 34176
#define OFF_BENC (OFF_WMU + LATENT*LATENT)      // 35200
#define OFF_BMU  (OFF_BENC + 32)                // 35232
#define OFF_BCH  (OFF_BMU + 32)                 // 35264 (544)
#define OFF_S    (OFF_BCH + NPAD)               // 35808
#define OFF_WBUF (OFF_S + 32)                   // 35840 (16B aligned)
#define SMEM_FLOATS (OFF_WBUF + WARPS*WBUF_FLOATS) // 53248 floats = 212992 B

#define MU_OFF  ((size_t)BATCH*LATENT)
#define COV_OFF ((size_t)BATCH*LATENT*2)

__device__ __forceinline__ float lrelu(float v) { return v >= 0.f ? v : 0.01f * v; }

__global__ void __launch_bounds__(THREADS)
pm_kernel(const float* __restrict__ x,       const float* __restrict__ W_enc,
          const float* __restrict__ b_enc,   const float* __restrict__ bn_gamma,
          const float* __restrict__ bn_beta, const float* __restrict__ bn_mean,
          const float* __restrict__ bn_var,  const float* __restrict__ W_mu,
          const float* __restrict__ b_mu,    const float* __restrict__ W_ch,
          const float* __restrict__ b_ch,    float* __restrict__ out)
{
    extern __shared__ float sm[];
    const int tid = threadIdx.x;

    // ---- stage + fold weights into smem ----
    if (tid < 32) {
        float s = bn_gamma[tid] * rsqrtf(bn_var[tid] + 1e-5f);
        sm[OFF_S + tid]    = s;
        sm[OFF_BENC + tid] = (b_enc[tid] - bn_mean[tid]) * s + bn_beta[tid];
        sm[OFF_BMU + tid]  = b_mu[tid];
    }
    __syncthreads();
    for (int idx = tid; idx < IN_DIM * LATENT; idx += THREADS) {
        int k = idx >> 5, j = idx & 31;
        sm[OFF_WENC + j * WENC_PAD + k] = W_enc[idx] * sm[OFF_S + j];  // transposed + BN fold
    }
    // W_ch col-pair interleave (R4/R12 proven): word w in row k:
    //   w < 512: cp=w>>6, ln=(w&63)>>1, s=w&1 -> col (2cp+s)*32+ln ; w>=512: col w (512..527, rest 0)
    for (int idx = tid; idx < LATENT * NPAD; idx += THREADS) {
        int k = idx / NPAD, w = idx - k * NPAD;
        float v;
        if (w < 512) {
            int cp = w >> 6, ln = (w & 63) >> 1, s = w & 1;
            v = W_ch[k * NTRI + (2 * cp + s) * 32 + ln];
        } else {
            v = (w < NTRI) ? W_ch[k * NTRI + w] : 0.f;
        }
        sm[OFF_WCH + idx] = v;
    }
    for (int idx = tid; idx < LATENT * LATENT; idx += THREADS) sm[OFF_WMU + idx] = W_mu[idx];
    for (int idx = tid; idx < NPAD; idx += THREADS) sm[OFF_BCH + idx] = (idx < NTRI) ? b_ch[idx] : 0.f;
    __syncthreads();

    const int warp = tid >> 5, lane = tid & 31;
    float* xw = sm + OFF_WBUF + warp * WBUF_FLOATS;   // x half stage / two L buffers
    const float* wrow = sm + OFF_WENC + lane * WENC_PAD;
    const float bj = sm[OFF_BENC + lane];
    const float bm = sm[OFF_BMU + lane];

    // cov half-split lane mapping (round-10 proven)
    const int ch   = lane & 15;                 // base column (0..15)
    const int ch2  = ch + 16;                   // high column
    float* Lbh = xw + (lane >> 4) * LOFF_B;     // own-half L buffer (A or B)
    const int triC  = (ch  * (ch  + 1)) >> 1;
    const int triC2 = (ch2 * (ch2 + 1)) >> 1;

    for (int tile = blockIdx.x; tile < NTILES; tile += gridDim.x) {
        const int rbase = tile * TILE_ROWS + warp * RPW;

        // ---- enc GEMM in two half-K passes (round-10 verbatim) ----
        float h0 = 0.f, h1 = 0.f, h2 = 0.f, h3 = 0.f;
        #pragma unroll
        for (int half = 0; half < 2; half++) {
            #pragma unroll
            for (int r = 0; r < RPW; r++) {
                const float4* xg = (const float4*)(x + (size_t)(rbase + r) * IN_DIM + half * 256);
                #pragma unroll
                for (int c = 0; c < 2; c++) {
                    float4 v = xg[c * 32 + lane];
                    *(float4*)(xw + r * XH + c * 128 + lane * 4) = v;
                }
            }
            __syncwarp();
            const float* wh = wrow + half * 256;
            #pragma unroll 4
            for (int k = 0; k < 256; k += 4) {
                float4 wv = *(const float4*)(wh + k);
                float4 a0 = *(const float4*)(xw + 0 * XH + k);
                float4 a1 = *(const float4*)(xw + 1 * XH + k);
                float4 a2 = *(const float4*)(xw + 2 * XH + k);
                float4 a3 = *(const float4*)(xw + 3 * XH + k);
                h0 = fmaf(a0.x, wv.x, h0); h0 = fmaf(a0.y, wv.y, h0); h0 = fmaf(a0.z, wv.z, h0); h0 = fmaf(a0.w, wv.w, h0);
                h1 = fmaf(a1.x, wv.x, h1); h1 = fmaf(a1.y, wv.y, h1); h1 = fmaf(a1.z, wv.z, h1); h1 = fmaf(a1.w, wv.w, h1);
                h2 = fmaf(a2.x, wv.x, h2); h2 = fmaf(a2.y, wv.y, h2); h2 = fmaf(a2.z, wv.z, h2); h2 = fmaf(a2.w, wv.w, h2);
                h3 = fmaf(a3.x, wv.x, h3); h3 = fmaf(a3.y, wv.y, h3); h3 = fmaf(a3.z, wv.z, h3); h3 = fmaf(a3.w, wv.w, h3);
            }
            __syncwarp();
        }
        h0 = lrelu(h0 + bj); h1 = lrelu(h1 + bj); h2 = lrelu(h2 + bj); h3 = lrelu(h3 + bj);
        out[(size_t)(rbase + 0) * 32 + lane] = h0;
        out[(size_t)(rbase + 1) * 32 + lane] = h1;
        out[(size_t)(rbase + 2) * 32 + lane] = h2;
        out[(size_t)(rbase + 3) * 32 + lane] = h3;

        // ---- mu + ch GEMMs: float2 W_ch loads, scalar FFMA ----
        float amu0 = 0.f, amu1 = 0.f, amu2 = 0.f, amu3 = 0.f;
        float2 ac2[RPW][8];          // .x -> chunk 2cp, .y -> chunk 2cp+1 (at position lane)
        float ac16[RPW];
        #pragma unroll
        for (int r = 0; r < RPW; r++) {
            ac16[r] = 0.f;
            #pragma unroll
            for (int cp = 0; cp < 8; cp++) ac2[r][cp] = make_float2(0.f, 0.f);
        }

        #pragma unroll 2
        for (int k = 0; k < LATENT; k++) {
            float hv0 = __shfl_sync(0xffffffffu, h0, k);
            float hv1 = __shfl_sync(0xffffffffu, h1, k);
            float hv2 = __shfl_sync(0xffffffffu, h2, k);
            float hv3 = __shfl_sync(0xffffffffu, h3, k);
            float wm = sm[OFF_WMU + k * 32 + lane];
            amu0 = fmaf(hv0, wm, amu0); amu1 = fmaf(hv1, wm, amu1);
            amu2 = fmaf(hv2, wm, amu2); amu3 = fmaf(hv3, wm, amu3);
            const float2* w2 = (const float2*)(sm + OFF_WCH + k * NPAD) + lane;
            #pragma unroll
            for (int cp = 0; cp < 8; cp++) {
                float2 w = w2[cp * 32];
                ac2[0][cp].x = fmaf(hv0, w.x, ac2[0][cp].x); ac2[0][cp].y = fmaf(hv0, w.y, ac2[0][cp].y);
                ac2[1][cp].x = fmaf(hv1, w.x, ac2[1][cp].x); ac2[1][cp].y = fmaf(hv1, w.y, ac2[1][cp].y);
                ac2[2][cp].x = fmaf(hv2, w.x, ac2[2][cp].x); ac2[2][cp].y = fmaf(hv2, w.y, ac2[2][cp].y);
                ac2[3][cp].x = fmaf(hv3, w.x, ac2[3][cp].x); ac2[3][cp].y = fmaf(hv3, w.y, ac2[3][cp].y);
            }
            float wc16 = sm[OFF_WCH + k * NPAD + 512 + lane];
            ac16[0] = fmaf(hv0, wc16, ac16[0]);
            ac16[1] = fmaf(hv1, wc16, ac16[1]);
            ac16[2] = fmaf(hv2, wc16, ac16[2]);
            ac16[3] = fmaf(hv3, wc16, ac16[3]);
        }
        out[MU_OFF + (size_t)(rbase + 0) * 32 + lane] = lrelu(amu0 + bm);
        out[MU_OFF + (size_t)(rbase + 1) * 32 + lane] = lrelu(amu1 + bm);
        out[MU_OFF + (size_t)(rbase + 2) * 32 + lane] = lrelu(amu2 + bm);
        out[MU_OFF + (size_t)(rbase + 3) * 32 + lane] = lrelu(amu3 + bm);
        __syncwarp();   // enc reads of xw done

        // ---- cov: 2 batch rows per pass via half-split broadcasts (round-10 proven) ----
        float* LbA = xw;            // packed-tri L of even row   [0, 528)
        float* LbB = xw + LOFF_B;   // packed-tri L of odd row    [560, 1088)
        #pragma unroll
        for (int p = 0; p < 2; p++) {
            // scatter elts for both rows; chunk cc value from ac2 (.x even, .y odd) / ac16
            #pragma unroll
            for (int cc = 0; cc < 17; cc++) {
                int e = cc * 32 + lane;
                if (cc == 16 && e >= NTRI) continue;
                float bc = sm[OFF_BCH + e];
                float vA, vB;
                if (cc < 16) {
                    float2 qA = ac2[2 * p + 0][cc >> 1];
                    float2 qB = ac2[2 * p + 1][cc >> 1];
                    if (cc & 1) { vA = qA.y; vB = qB.y; }
                    else        { vA = qA.x; vB = qB.x; }
                } else { vA = ac16[2 * p]; vB = ac16[2 * p + 1]; }
                LbA[e] = lrelu(vA + bc);
                LbB[e] = lrelu(vB + bc);
            }
            __syncwarp();
            // diag transform (lane = L-row), both buffers
            {
                int dio = ((lane * (lane + 1)) >> 1) + lane;
                float d = LbA[dio];
                float sp = (d > 20.f) ? d : log1pf(expf(d));
                LbA[dio] = fminf(fmaxf(sp, 0.001f), 100.f) + 0.01f;
                d = LbB[dio];
                sp = (d > 20.f) ? d : log1pf(expf(d));
                LbB[dio] = fminf(fmaxf(sp, 0.001f), 100.f) + 0.01f;
            }
            __syncwarp();
            // gather own rows (cols ch, ch+16) from own-half buffer; zeros beyond row end
            float Lk1[16], Lk2[32];
            #pragma unroll
            for (int j = 0; j < 16; j++) Lk1[j] = (j <= ch)  ? Lbh[triC  + j] : 0.f;
            #pragma unroll
            for (int j = 0; j < 32; j++) Lk2[j] = (j <= ch2) ? Lbh[triC2 + j] : 0.f;

            float* oc = out + COV_OFF + (size_t)(rbase + 2 * p + (lane >> 4)) * 1024;
            #pragma unroll
            for (int i = 0; i < 32; i++) {
                const float* Lr = Lbh + ((i * (i + 1)) >> 1);
                float a1a = 0.f, a1b = 0.f, a2a = 0.f, a2b = 0.f;
                #pragma unroll
                for (int j = 0; j <= i; j++) {
                    float lv = Lr[j];               // half-split broadcast: 1 wf for both rows
                    if (j < 16) {
                        if (j & 1) a1b = fmaf(Lk1[j], lv, a1b);
                        else       a1a = fmaf(Lk1[j], lv, a1a);
                    }
                    if (j & 1) a2b = fmaf(Lk2[j], lv, a2b);
                    else       a2a = fmaf(Lk2[j], lv, a2a);
                }
                float cv1 = a1a + a1b;
                float cv2 = a2a + a2b;
                if (i == ch)  cv1 += 0.01f;
                if (i == ch2) cv2 += 0.01f;
                oc[i * 32 + ch]  = cv1;
                oc[i * 32 + ch2] = cv2;
            }
            __syncwarp();   // cov reads done before next scatter / next tile x stage
        }
    }
}

extern "C" void kernel_launch(void* const* d_in, const int* in_sizes, int n_in,
                              void* d_out, int out_size)
{
    (void)in_sizes; (void)n_in; (void)out_size;
    const float* x        = (const float*)d_in[0];
    const float* W_enc    = (const float*)d_in[1];
    const float* b_enc    = (const float*)d_in[2];
    const float* bn_gamma = (const float*)d_in[3];
    const float* bn_beta  = (const float*)d_in[4];
    const float* bn_mean  = (const float*)d_in[5];
    const float* bn_var   = (const float*)d_in[6];
    const float* W_mu     = (const float*)d_in[7];
    const float* b_mu     = (const float*)d_in[8];
    const float* W_ch     = (const float*)d_in[9];
    const float* b_ch     = (const float*)d_in[10];
    float* out = (float*)d_out;

    cudaFuncSetAttribute(pm_kernel, cudaFuncAttributeMaxDynamicSharedMemorySize,
                         SMEM_FLOATS * (int)sizeof(float));
    pm_kernel<<<GRID, THREADS, SMEM_FLOATS * sizeof(float)>>>(
        x, W_enc, b_enc, bn_gamma, bn_beta, bn_mean, bn_var,
        W_mu, b_mu, W_ch, b_ch, out);
}

// round 16
// speedup vs baseline: 1.2214x; 1.0354x over previous
#include <cuda_runtime.h>
#include <math.h>
#include <stdint.h>

#define BATCH   65536
#define IN_DIM  512
#define LATENT  32
#define NTRI    528
#define NPAD    544            // W_ch padded row (floats)
#define WENC_PAD 524           // conflict-free float4 weight rows
#define THREADS 512
#define WARPS   16
#define RPW     4
#define TILE_ROWS (WARPS*RPW)  // 64
#define NTILES  (BATCH/TILE_ROWS) // 1024
#define GRID    152

#define XH      272            // per-row stride (floats) of half-K x stage
#define LOFF_B  560            // cov buffer-B offset (bank set differs by 16 from A)
#define WBUF_FLOATS 1088       // per-warp buffer: 4x272 x-halves OR two packed-tri L rows

// ---- smem layout (floats) ----
#define OFF_WENC 0
#define SZ_WENC  (LATENT*WENC_PAD)              // 16768
#define OFF_WCH  (OFF_WENC + SZ_WENC)           // 16768
#define SZ_WCH   (LATENT*NPAD)                  // 17408
#define OFF_WMU  (OFF_WCH + SZ_WCH)             // 34176
#define OFF_BENC (OFF_WMU + LATENT*LATENT)      // 35200
#define OFF_BMU  (OFF_BENC + 32)                // 35232
#define OFF_BCH  (OFF_BMU + 32)                 // 35264 (544)
#define OFF_S    (OFF_BCH + NPAD)               // 35808
#define OFF_WBUF (OFF_S + 32)                   // 35840 (16B aligned)
#define SMEM_FLOATS (OFF_WBUF + WARPS*WBUF_FLOATS) // 53248 floats = 212992 B

#define MU_OFF  ((size_t)BATCH*LATENT)
#define COV_OFF ((size_t)BATCH*LATENT*2)

__device__ __forceinline__ float lrelu(float v) { return v >= 0.f ? v : 0.01f * v; }

__global__ void __launch_bounds__(THREADS)
pm_kernel(const float* __restrict__ x,       const float* __restrict__ W_enc,
          const float* __restrict__ b_enc,   const float* __restrict__ bn_gamma,
          const float* __restrict__ bn_beta, const float* __restrict__ bn_mean,
          const float* __restrict__ bn_var,  const float* __restrict__ W_mu,
          const float* __restrict__ b_mu,    const float* __restrict__ W_ch,
          const float* __restrict__ b_ch,    float* __restrict__ out)
{
    extern __shared__ float sm[];
    const int tid = threadIdx.x;

    // ---- stage + fold weights into smem ----
    if (tid < 32) {
        float s = bn_gamma[tid] * rsqrtf(bn_var[tid] + 1e-5f);
        sm[OFF_S + tid]    = s;
        sm[OFF_BENC + tid] = (b_enc[tid] - bn_mean[tid]) * s + bn_beta[tid];
        sm[OFF_BMU + tid]  = b_mu[tid];
    }
    __syncthreads();
    for (int idx = tid; idx < IN_DIM * LATENT; idx += THREADS) {
        int k = idx >> 5, j = idx & 31;
        sm[OFF_WENC + j * WENC_PAD + k] = W_enc[idx] * sm[OFF_S + j];  // transposed + BN fold
    }
    for (int idx = tid; idx < LATENT * NPAD; idx += THREADS) {
        int k = idx / NPAD, c = idx - k * NPAD;
        sm[OFF_WCH + idx] = (c < NTRI) ? W_ch[k * NTRI + c] : 0.f;
    }
    for (int idx = tid; idx < LATENT * LATENT; idx += THREADS) sm[OFF_WMU + idx] = W_mu[idx];
    for (int idx = tid; idx < NPAD; idx += THREADS) sm[OFF_BCH + idx] = (idx < NTRI) ? b_ch[idx] : 0.f;
    __syncthreads();

    const int warp = tid >> 5, lane = tid & 31;
    float* xw = sm + OFF_WBUF + warp * WBUF_FLOATS;   // x half stage / two L buffers
    const float* wrow = sm + OFF_WENC + lane * WENC_PAD;
    const float bj = sm[OFF_BENC + lane];
    const float bm = sm[OFF_BMU + lane];

    // cov half-split lane mapping
    const int ch   = lane & 15;                 // base column (0..15)
    const int ch2  = ch + 16;                   // high column
    float* Lbh = xw + (lane >> 4) * LOFF_B;     // own-half L buffer (A or B)
    const int triC  = (ch  * (ch  + 1)) >> 1;
    const int triC2 = (ch2 * (ch2 + 1)) >> 1;

    for (int tile = blockIdx.x; tile < NTILES; tile += gridDim.x) {
        const int rbase = tile * TILE_ROWS + warp * RPW;

        // ---- enc GEMM in two half-K passes ----
        float h0 = 0.f, h1 = 0.f, h2 = 0.f, h3 = 0.f;
        #pragma unroll
        for (int half = 0; half < 2; half++) {
            // stage x[4][256] (coalesced float4)
            #pragma unroll
            for (int r = 0; r < RPW; r++) {
                const float4* xg = (const float4*)(x + (size_t)(rbase + r) * IN_DIM + half * 256);
                #pragma unroll
                for (int c = 0; c < 2; c++) {
                    float4 v = xg[c * 32 + lane];
                    *(float4*)(xw + r * XH + c * 128 + lane * 4) = v;
                }
            }
            __syncwarp();
            const float* wh = wrow + half * 256;
            #pragma unroll 4
            for (int k = 0; k < 256; k += 4) {
                float4 wv = *(const float4*)(wh + k);
                float4 a0 = *(const float4*)(xw + 0 * XH + k);
                float4 a1 = *(const float4*)(xw + 1 * XH + k);
                float4 a2 = *(const float4*)(xw + 2 * XH + k);
                float4 a3 = *(const float4*)(xw + 3 * XH + k);
                h0 = fmaf(a0.x, wv.x, h0); h0 = fmaf(a0.y, wv.y, h0); h0 = fmaf(a0.z, wv.z, h0); h0 = fmaf(a0.w, wv.w, h0);
                h1 = fmaf(a1.x, wv.x, h1); h1 = fmaf(a1.y, wv.y, h1); h1 = fmaf(a1.z, wv.z, h1); h1 = fmaf(a1.w, wv.w, h1);
                h2 = fmaf(a2.x, wv.x, h2); h2 = fmaf(a2.y, wv.y, h2); h2 = fmaf(a2.z, wv.z, h2); h2 = fmaf(a2.w, wv.w, h2);
                h3 = fmaf(a3.x, wv.x, h3); h3 = fmaf(a3.y, wv.y, h3); h3 = fmaf(a3.z, wv.z, h3); h3 = fmaf(a3.w, wv.w, h3);
            }
            __syncwarp();   // done reading this half before restaging / L reuse
        }
        h0 = lrelu(h0 + bj); h1 = lrelu(h1 + bj); h2 = lrelu(h2 + bj); h3 = lrelu(h3 + bj);
        out[(size_t)(rbase + 0) * 32 + lane] = h0;
        out[(size_t)(rbase + 1) * 32 + lane] = h1;
        out[(size_t)(rbase + 2) * 32 + lane] = h2;
        out[(size_t)(rbase + 3) * 32 + lane] = h3;

        // ---- mu + ch GEMMs (scalar) ----
        float amu0 = 0.f, amu1 = 0.f, amu2 = 0.f, amu3 = 0.f;
        float ac[RPW][17];
        #pragma unroll
        for (int r = 0; r < RPW; r++)
            #pragma unroll
            for (int c = 0; c < 17; c++) ac[r][c] = 0.f;

        #pragma unroll 2
        for (int k = 0; k < LATENT; k++) {
            float hv0 = __shfl_sync(0xffffffffu, h0, k);
            float hv1 = __shfl_sync(0xffffffffu, h1, k);
            float hv2 = __shfl_sync(0xffffffffu, h2, k);
            float hv3 = __shfl_sync(0xffffffffu, h3, k);
            float wm = sm[OFF_WMU + k * 32 + lane];
            amu0 = fmaf(hv0, wm, amu0); amu1 = fmaf(hv1, wm, amu1);
            amu2 = fmaf(hv2, wm, amu2); amu3 = fmaf(hv3, wm, amu3);
            const float* wck = sm + OFF_WCH + k * NPAD + lane;
            #pragma unroll
            for (int c = 0; c < 17; c++) {
                float wc = wck[c * 32];
                ac[0][c] = fmaf(hv0, wc, ac[0][c]);
                ac[1][c] = fmaf(hv1, wc, ac[1][c]);
                ac[2][c] = fmaf(hv2, wc, ac[2][c]);
                ac[3][c] = fmaf(hv3, wc, ac[3][c]);
            }
        }
        out[MU_OFF + (size_t)(rbase + 0) * 32 + lane] = lrelu(amu0 + bm);
        out[MU_OFF + (size_t)(rbase + 1) * 32 + lane] = lrelu(amu1 + bm);
        out[MU_OFF + (size_t)(rbase + 2) * 32 + lane] = lrelu(amu2 + bm);
        out[MU_OFF + (size_t)(rbase + 3) * 32 + lane] = lrelu(amu3 + bm);
        __syncwarp();   // enc reads of xw done

        // ---- cov: 2 batch rows per pass via half-split broadcasts ----
        float* LbA = xw;            // packed-tri L of even row   [0, 528)
        float* LbB = xw + LOFF_B;   // packed-tri L of odd row    [560, 1088)
        #pragma unroll
        for (int p = 0; p < 2; p++) {
            // scatter elts for both rows (full warp, packed-tri offset == element index)
            #pragma unroll
            for (int cc = 0; cc < 17; cc++) {
                int e = cc * 32 + lane;
                if (cc == 16 && e >= NTRI) continue;
                float bc = sm[OFF_BCH + e];
                LbA[e] = lrelu(ac[2 * p + 0][cc] + bc);
                LbB[e] = lrelu(ac[2 * p + 1][cc] + bc);
            }
            __syncwarp();
            // diag transform (lane = L-row), both buffers
            {
                int dio = ((lane * (lane + 1)) >> 1) + lane;
                float d = LbA[dio];
                float sp = (d > 20.f) ? d : log1pf(expf(d));
                LbA[dio] = fminf(fmaxf(sp, 0.001f), 100.f) + 0.01f;
                d = LbB[dio];
                sp = (d > 20.f) ? d : log1pf(expf(d));
                LbB[dio] = fminf(fmaxf(sp, 0.001f), 100.f) + 0.01f;
            }
            __syncwarp();
            // gather own rows (cols ch, ch+16) from own-half buffer; zeros beyond row end
            float Lk1[16], Lk2[32];
            #pragma unroll
            for (int j = 0; j < 16; j++) Lk1[j] = (j <= ch)  ? Lbh[triC  + j] : 0.f;
            #pragma unroll
            for (int j = 0; j < 32; j++) Lk2[j] = (j <= ch2) ? Lbh[triC2 + j] : 0.f;

            float* oc = out + COV_OFF + (size_t)(rbase + 2 * p + (lane >> 4)) * 1024;
            #pragma unroll
            for (int i = 0; i < 32; i++) {
                const float* Lr = Lbh + ((i * (i + 1)) >> 1);
                float a1a = 0.f, a1b = 0.f, a2a = 0.f, a2b = 0.f;
                #pragma unroll
                for (int j = 0; j <= i; j++) {
                    float lv = Lr[j];               // half-split broadcast: 1 wf for both rows
                    if (j < 16) {
                        if (j & 1) a1b = fmaf(Lk1[j], lv, a1b);
                        else       a1a = fmaf(Lk1[j], lv, a1a);
                    }
                    if (j & 1) a2b = fmaf(Lk2[j], lv, a2b);
                    else       a2a = fmaf(Lk2[j], lv, a2a);
                }
                float cv1 = a1a + a1b;
                float cv2 = a2a + a2b;
                if (i == ch)  cv1 += 0.01f;
                if (i == ch2) cv2 += 0.01f;
                oc[i * 32 + ch]  = cv1;
                oc[i * 32 + ch2] = cv2;
            }
            __syncwarp();   // cov reads done before next scatter / next tile x stage
        }
    }
}

extern "C" void kernel_launch(void* const* d_in, const int* in_sizes, int n_in,
                              void* d_out, int out_size)
{
    (void)in_sizes; (void)n_in; (void)out_size;
    const float* x        = (const float*)d_in[0];
    const float* W_enc    = (const float*)d_in[1];
    const float* b_enc    = (const float*)d_in[2];
    const float* bn_gamma = (const float*)d_in[3];
    const float* bn_beta  = (const float*)d_in[4];
    const float* bn_mean  = (const float*)d_in[5];
    const float* bn_var   = (const float*)d_in[6];
    const float* W_mu     = (const float*)d_in[7];
    const float* b_mu     = (const float*)d_in[8];
    const float* W_ch     = (const float*)d_in[9];
    const float* b_ch     = (const float*)d_in[10];
    float* out = (float*)d_out;

    cudaFuncSetAttribute(pm_kernel, cudaFuncAttributeMaxDynamicSharedMemorySize,
                         SMEM_FLOATS * (int)sizeof(float));
    pm_kernel<<<GRID, THREADS, SMEM_FLOATS * sizeof(float)>>>(
        x, W_enc, b_enc, bn_gamma, bn_beta, bn_mean, bn_var,
        W_mu, b_mu, W_ch, b_ch, out);
}

// round 17
// speedup vs baseline: 1.2581x; 1.0301x over previous
#include <cuda_runtime.h>
#include <math.h>
#include <stdint.h>

#define BATCH   65536
#define IN_DIM  512
#define LATENT  32
#define NTRI    528
#define NPAD    544            // W_ch padded row (floats)
#define WENC_PAD 524           // conflict-free float4 weight rows
#define THREADS 512
#define WARPS   16
#define RPW     4
#define TILE_ROWS (WARPS*RPW)  // 64
#define NTILES  (BATCH/TILE_ROWS) // 1024
#define GRID    152

#define XH      272            // per-row stride (floats) of half-K x stage
#define LOFF_B  560            // cov buffer-B offset (bank set differs by 16 from A)
#define WBUF_FLOATS 1088       // per-warp buffer: 4x272 x-halves OR two packed-tri L rows

// ---- smem layout (floats) ----
#define OFF_WENC 0
#define SZ_WENC  (LATENT*WENC_PAD)              // 16768
#define OFF_WCH  (OFF_WENC + SZ_WENC)           // 16768
#define SZ_WCH   (LATENT*NPAD)                  // 17408
#define OFF_WMU  (OFF_WCH + SZ_WCH)             // 34176
#define OFF_BENC (OFF_WMU + LATENT*LATENT)      // 35200
#define OFF_BMU  (OFF_BENC + 32)                // 35232
#define OFF_BCH  (OFF_BMU + 32)                 // 35264 (544)
#define OFF_S    (OFF_BCH + NPAD)               // 35808
#define OFF_WBUF (OFF_S + 32)                   // 35840 (16B aligned)
#define SMEM_FLOATS (OFF_WBUF + WARPS*WBUF_FLOATS) // 53248 floats = 212992 B

#define MU_OFF  ((size_t)BATCH*LATENT)
#define COV_OFF ((size_t)BATCH*LATENT*2)

__device__ __forceinline__ float lrelu(float v) { return v >= 0.f ? v : 0.01f * v; }

__device__ __forceinline__ unsigned smem_u32(const void* p) {
    unsigned a;
    asm("{ .reg .u64 t; cvta.to.shared.u64 t, %1; cvt.u32.u64 %0, t; }" : "=r"(a) : "l"(p));
    return a;
}
__device__ __forceinline__ void cp16(unsigned dst, const void* src) {
    asm volatile("cp.async.cg.shared.global [%0], [%1], 16;" :: "r"(dst), "l"(src) : "memory");
}
__device__ __forceinline__ void cp_commit_wait() {
    asm volatile("cp.async.commit_group;" ::: "memory");
    asm volatile("cp.async.wait_group 0;" ::: "memory");
}

__global__ void __launch_bounds__(THREADS)
pm_kernel(const float* __restrict__ x,       const float* __restrict__ W_enc,
          const float* __restrict__ b_enc,   const float* __restrict__ bn_gamma,
          const float* __restrict__ bn_beta, const float* __restrict__ bn_mean,
          const float* __restrict__ bn_var,  const float* __restrict__ W_mu,
          const float* __restrict__ b_mu,    const float* __restrict__ W_ch,
          const float* __restrict__ b_ch,    float* __restrict__ out)
{
    extern __shared__ float sm[];
    const int tid = threadIdx.x;

    // ---- stage + fold weights into smem ----
    if (tid < 32) {
        float s = bn_gamma[tid] * rsqrtf(bn_var[tid] + 1e-5f);
        sm[OFF_S + tid]    = s;
        sm[OFF_BENC + tid] = (b_enc[tid] - bn_mean[tid]) * s + bn_beta[tid];
        sm[OFF_BMU + tid]  = b_mu[tid];
    }
    __syncthreads();
    for (int idx = tid; idx < IN_DIM * LATENT; idx += THREADS) {
        int k = idx >> 5, j = idx & 31;
        sm[OFF_WENC + j * WENC_PAD + k] = W_enc[idx] * sm[OFF_S + j];  // transposed + BN fold
    }
    for (int idx = tid; idx < LATENT * NPAD; idx += THREADS) {
        int k = idx / NPAD, c = idx - k * NPAD;
        sm[OFF_WCH + idx] = (c < NTRI) ? W_ch[k * NTRI + c] : 0.f;
    }
    for (int idx = tid; idx < LATENT * LATENT; idx += THREADS) sm[OFF_WMU + idx] = W_mu[idx];
    for (int idx = tid; idx < NPAD; idx += THREADS) sm[OFF_BCH + idx] = (idx < NTRI) ? b_ch[idx] : 0.f;
    __syncthreads();

    const int warp = tid >> 5, lane = tid & 31;
    float* xw = sm + OFF_WBUF + warp * WBUF_FLOATS;   // x half stage / two L buffers
    const unsigned xw_s = smem_u32(xw);
    const float* wrow = sm + OFF_WENC + lane * WENC_PAD;
    const float bj = sm[OFF_BENC + lane];
    const float bm = sm[OFF_BMU + lane];

    // cov half-split lane mapping
    const int ch   = lane & 15;                 // base column (0..15)
    const int ch2  = ch + 16;                   // high column
    float* Lbh = xw + (lane >> 4) * LOFF_B;     // own-half L buffer (A or B)
    const int triC  = (ch  * (ch  + 1)) >> 1;
    const int triC2 = (ch2 * (ch2 + 1)) >> 1;

    for (int tile = blockIdx.x; tile < NTILES; tile += gridDim.x) {
        const int rbase = tile * TILE_ROWS + warp * RPW;

        // ---- enc GEMM in two half-K passes (cp.async staging) ----
        float h0 = 0.f, h1 = 0.f, h2 = 0.f, h3 = 0.f;
        #pragma unroll
        for (int half = 0; half < 2; half++) {
            // stage x[4][256] via cp.async (16B per lane per chunk)
            #pragma unroll
            for (int r = 0; r < RPW; r++) {
                const float* xs = x + (size_t)(rbase + r) * IN_DIM + half * 256;
                #pragma unroll
                for (int c = 0; c < 2; c++)
                    cp16(xw_s + (r * XH + c * 128 + lane * 4) * 4, xs + c * 128 + lane * 4);
            }
            cp_commit_wait();
            __syncwarp();
            const float* wh = wrow + half * 256;
            #pragma unroll 4
            for (int k = 0; k < 256; k += 4) {
                float4 wv = *(const float4*)(wh + k);
                float4 a0 = *(const float4*)(xw + 0 * XH + k);
                float4 a1 = *(const float4*)(xw + 1 * XH + k);
                float4 a2 = *(const float4*)(xw + 2 * XH + k);
                float4 a3 = *(const float4*)(xw + 3 * XH + k);
                h0 = fmaf(a0.x, wv.x, h0); h0 = fmaf(a0.y, wv.y, h0); h0 = fmaf(a0.z, wv.z, h0); h0 = fmaf(a0.w, wv.w, h0);
                h1 = fmaf(a1.x, wv.x, h1); h1 = fmaf(a1.y, wv.y, h1); h1 = fmaf(a1.z, wv.z, h1); h1 = fmaf(a1.w, wv.w, h1);
                h2 = fmaf(a2.x, wv.x, h2); h2 = fmaf(a2.y, wv.y, h2); h2 = fmaf(a2.z, wv.z, h2); h2 = fmaf(a2.w, wv.w, h2);
                h3 = fmaf(a3.x, wv.x, h3); h3 = fmaf(a3.y, wv.y, h3); h3 = fmaf(a3.z, wv.z, h3); h3 = fmaf(a3.w, wv.w, h3);
            }
            __syncwarp();   // done reading this half before restaging / L reuse
        }
        h0 = lrelu(h0 + bj); h1 = lrelu(h1 + bj); h2 = lrelu(h2 + bj); h3 = lrelu(h3 + bj);
        out[(size_t)(rbase + 0) * 32 + lane] = h0;
        out[(size_t)(rbase + 1) * 32 + lane] = h1;
        out[(size_t)(rbase + 2) * 32 + lane] = h2;
        out[(size_t)(rbase + 3) * 32 + lane] = h3;

        // ---- mu + ch GEMMs (scalar) ----
        float amu0 = 0.f, amu1 = 0.f, amu2 = 0.f, amu3 = 0.f;
        float ac[RPW][17];
        #pragma unroll
        for (int r = 0; r < RPW; r++)
            #pragma unroll
            for (int c = 0; c < 17; c++) ac[r][c] = 0.f;

        #pragma unroll 2
        for (int k = 0; k < LATENT; k++) {
            float hv0 = __shfl_sync(0xffffffffu, h0, k);
            float hv1 = __shfl_sync(0xffffffffu, h1, k);
            float hv2 = __shfl_sync(0xffffffffu, h2, k);
            float hv3 = __shfl_sync(0xffffffffu, h3, k);
            float wm = sm[OFF_WMU + k * 32 + lane];
            amu0 = fmaf(hv0, wm, amu0); amu1 = fmaf(hv1, wm, amu1);
            amu2 = fmaf(hv2, wm, amu2); amu3 = fmaf(hv3, wm, amu3);
            const float* wck = sm + OFF_WCH + k * NPAD + lane;
            #pragma unroll
            for (int c = 0; c < 17; c++) {
                float wc = wck[c * 32];
                ac[0][c] = fmaf(hv0, wc, ac[0][c]);
                ac[1][c] = fmaf(hv1, wc, ac[1][c]);
                ac[2][c] = fmaf(hv2, wc, ac[2][c]);
                ac[3][c] = fmaf(hv3, wc, ac[3][c]);
            }
        }
        out[MU_OFF + (size_t)(rbase + 0) * 32 + lane] = lrelu(amu0 + bm);
        out[MU_OFF + (size_t)(rbase + 1) * 32 + lane] = lrelu(amu1 + bm);
        out[MU_OFF + (size_t)(rbase + 2) * 32 + lane] = lrelu(amu2 + bm);
        out[MU_OFF + (size_t)(rbase + 3) * 32 + lane] = lrelu(amu3 + bm);
        __syncwarp();   // enc reads of xw done

        // ---- cov: 2 batch rows per pass via half-split broadcasts ----
        float* LbA = xw;            // packed-tri L of even row   [0, 528)
        float* LbB = xw + LOFF_B;   // packed-tri L of odd row    [560, 1088)
        #pragma unroll
        for (int p = 0; p < 2; p++) {
            // scatter elts for both rows (full warp, packed-tri offset == element index)
            #pragma unroll
            for (int cc = 0; cc < 17; cc++) {
                int e = cc * 32 + lane;
                if (cc == 16 && e >= NTRI) continue;
                float bc = sm[OFF_BCH + e];
                LbA[e] = lrelu(ac[2 * p + 0][cc] + bc);
                LbB[e] = lrelu(ac[2 * p + 1][cc] + bc);
            }
            __syncwarp();
            // diag transform (lane = L-row), both buffers
            {
                int dio = ((lane * (lane + 1)) >> 1) + lane;
                float d = LbA[dio];
                float sp = (d > 20.f) ? d : log1pf(expf(d));
                LbA[dio] = fminf(fmaxf(sp, 0.001f), 100.f) + 0.01f;
                d = LbB[dio];
                sp = (d > 20.f) ? d : log1pf(expf(d));
                LbB[dio] = fminf(fmaxf(sp, 0.001f), 100.f) + 0.01f;
            }
            __syncwarp();
            // gather own rows (cols ch, ch+16) from own-half buffer; zeros beyond row end
            float Lk1[16], Lk2[32];
            #pragma unroll
            for (int j = 0; j < 16; j++) Lk1[j] = (j <= ch)  ? Lbh[triC  + j] : 0.f;
            #pragma unroll
            for (int j = 0; j < 32; j++) Lk2[j] = (j <= ch2) ? Lbh[triC2 + j] : 0.f;

            float* oc = out + COV_OFF + (size_t)(rbase + 2 * p + (lane >> 4)) * 1024;
            #pragma unroll
            for (int i = 0; i < 32; i++) {
                const float* Lr = Lbh + ((i * (i + 1)) >> 1);
                float a1a = 0.f, a1b = 0.f, a2a = 0.f, a2b = 0.f;
                #pragma unroll
                for (int j = 0; j <= i; j++) {
                    float lv = Lr[j];               // half-split broadcast: 1 wf for both rows
                    if (j < 16) {
                        if (j & 1) a1b = fmaf(Lk1[j], lv, a1b);
                        else       a1a = fmaf(Lk1[j], lv, a1a);
                    }
                    if (j & 1) a2b = fmaf(Lk2[j], lv, a2b);
                    else       a2a = fmaf(Lk2[j], lv, a2a);
                }
                float cv1 = a1a + a1b;
                float cv2 = a2a + a2b;
                if (i == ch)  cv1 += 0.01f;
                if (i == ch2) cv2 += 0.01f;
                oc[i * 32 + ch]  = cv1;
                oc[i * 32 + ch2] = cv2;
            }
            __syncwarp();   // cov reads done before next scatter / next tile x stage
        }
    }
}

extern "C" void kernel_launch(void* const* d_in, const int* in_sizes, int n_in,
                              void* d_out, int out_size)
{
    (void)in_sizes; (void)n_in; (void)out_size;
    const float* x        = (const float*)d_in[0];
    const float* W_enc    = (const float*)d_in[1];
    const float* b_enc    = (const float*)d_in[2];
    const float* bn_gamma = (const float*)d_in[3];
    const float* bn_beta  = (const float*)d_in[4];
    const float* bn_mean  = (const float*)d_in[5];
    const float* bn_var   = (const float*)d_in[6];
    const float* W_mu     = (const float*)d_in[7];
    const float* b_mu     = (const float*)d_in[8];
    const float* W_ch     = (const float*)d_in[9];
    const float* b_ch     = (const float*)d_in[10];
    float* out = (float*)d_out;

    cudaFuncSetAttribute(pm_kernel, cudaFuncAttributeMaxDynamicSharedMemorySize,
                         SMEM_FLOATS * (int)sizeof(float));
    pm_kernel<<<GRID, THREADS, SMEM_FLOATS * sizeof(float)>>>(
        x, W_enc, b_enc, bn_gamma, bn_beta, bn_mean, bn_var,
        W_mu, b_mu, W_ch, b_ch, out);
}